// round 7
// baseline (speedup 1.0000x reference)
#include <cuda_runtime.h>
#include <cuda_bf16.h>
#include <cstdint>
#include <cstddef>

#define BATCH   4
#define SLEN    4096
#define DDIM    1024
#define MTOT    (BATCH * SLEN)          // 16384

typedef __nv_bfloat16  bf16;
typedef __nv_bfloat162 bf162;

// ---------------------------------------------------------------------------
// Scratch (allocation-free rule: __device__ globals). All operands pre-split
// into bf16 hi/lo pairs so GEMM mainloops are pure bf16.
// ---------------------------------------------------------------------------
__device__ bf16 g_xhi [(size_t)MTOT * DDIM];
__device__ bf16 g_xlo [(size_t)MTOT * DDIM];
__device__ bf16 g_Wqhi[(size_t)DDIM * DDIM];
__device__ bf16 g_Wqlo[(size_t)DDIM * DDIM];
__device__ bf16 g_Wkhi[(size_t)DDIM * DDIM];
__device__ bf16 g_Wklo[(size_t)DDIM * DDIM];
__device__ bf16 g_Wvhi[(size_t)DDIM * DDIM];
__device__ bf16 g_Wvlo[(size_t)DDIM * DDIM];
__device__ bf16 g_Qhi [(size_t)MTOT * DDIM];
__device__ bf16 g_Qlo [(size_t)MTOT * DDIM];
__device__ bf16 g_Khi [(size_t)MTOT * DDIM];
__device__ bf16 g_Klo [(size_t)MTOT * DDIM];
__device__ bf16 g_Vthi[(size_t)DDIM * MTOT];   // V transposed [D, MTOT]
__device__ bf16 g_Vtlo[(size_t)DDIM * MTOT];
__device__ float g_S  [(size_t)MTOT * SLEN];   // fp32 scores (softmax input)
__device__ bf16 g_Phi [(size_t)MTOT * SLEN];
__device__ bf16 g_Plo [(size_t)MTOT * SLEN];

// ---------------------------------------------------------------------------
// Helpers (arch-agnostic PTX only: plain sm_103 target)
// ---------------------------------------------------------------------------
__device__ __forceinline__ uint32_t smem_u32(const void* p) {
    uint32_t a;
    asm("{ .reg .u64 t; cvta.to.shared.u64 t, %1; cvt.u32.u64 %0, t; }" : "=r"(a) : "l"(p));
    return a;
}
__device__ __forceinline__ void ldsm4(uint32_t& r0, uint32_t& r1, uint32_t& r2, uint32_t& r3,
                                      uint32_t addr) {
    asm volatile("ldmatrix.sync.aligned.m8n8.x4.shared.b16 {%0,%1,%2,%3}, [%4];"
                 : "=r"(r0), "=r"(r1), "=r"(r2), "=r"(r3) : "r"(addr));
}
__device__ __forceinline__ void mma16816(float* c, const uint32_t* a, const uint32_t* b) {
    asm volatile(
        "mma.sync.aligned.m16n8k16.row.col.f32.bf16.bf16.f32 "
        "{%0,%1,%2,%3}, {%4,%5,%6,%7}, {%8,%9}, {%0,%1,%2,%3};"
        : "+f"(c[0]), "+f"(c[1]), "+f"(c[2]), "+f"(c[3])
        : "r"(a[0]), "r"(a[1]), "r"(a[2]), "r"(a[3]), "r"(b[0]), "r"(b[1]));
}
__device__ __forceinline__ void cpasync16(uint32_t dst, const void* src) {
    asm volatile("cp.async.cg.shared.global [%0], [%1], 16;" :: "r"(dst), "l"(src));
}
__device__ __forceinline__ void split2(float x, float y, bf162& h, bf162& l) {
    h = __floats2bfloat162_rn(x, y);
    float2 f = __bfloat1622float2(h);
    l = __floats2bfloat162_rn(x - f.x, y - f.y);
}

// ---------------------------------------------------------------------------
// fp32 -> bf16 hi/lo split (elementwise). n divisible by 1024.
// ---------------------------------------------------------------------------
__global__ __launch_bounds__(256) void conv_split(
    const float* __restrict__ src, bf16* __restrict__ hi, bf16* __restrict__ lo)
{
    size_t i = ((size_t)blockIdx.x * 256 + threadIdx.x) * 4;
    float4 v = *(const float4*)(src + i);
    bf162 h0, l0, h1, l1;
    split2(v.x, v.y, h0, l0);
    split2(v.z, v.w, h1, l1);
    *(bf162*)(hi + i)     = h0;
    *(bf162*)(hi + i + 2) = h1;
    *(bf162*)(lo + i)     = l0;
    *(bf162*)(lo + i + 2) = l1;
}

// ---------------------------------------------------------------------------
// Pure-bf16 NT GEMM (3-pass fp32 emulation): C = sum_k A[m,k]*B[n,k]
// CTA tile 256x128, warp tile 64x64 (4 m-warps x 2 n-warps), K-chunk 64,
// 2-stage cp.async pipeline, one __syncthreads per chunk. 256 threads.
// mode 0: fp32 C.  mode 1: bf16 hi/lo row-major.  mode 2: bf16 hi/lo transposed.
// ---------------------------------------------------------------------------
#define KC       64
#define LDT      72                         // padded row stride (bf16) -> 144 B
#define A_MAT    (256 * LDT * 2)            // 36864 B (256 rows)
#define B_MAT    (128 * LDT * 2)            // 18432 B (128 rows)
#define OFF_AHI  0
#define OFF_ALO  (A_MAT)
#define OFF_BHI  (2 * A_MAT)
#define OFF_BLO  (2 * A_MAT + B_MAT)
#define STAGE_B  (2 * A_MAT + 2 * B_MAT)    // 110592 B
#define SMEM_DYN (2 * STAGE_B)              // 221184 B

__global__ __launch_bounds__(256, 1) void gemm_bf(
    const bf16* __restrict__ Ahi, const bf16* __restrict__ Alo,
    const bf16* __restrict__ Bhi, const bf16* __restrict__ Blo,
    float* __restrict__ Cf, bf16* __restrict__ Chi, bf16* __restrict__ Clo,
    int lda, int ldb, int ldc, int K, int mode,
    size_t sA, size_t sB, size_t sC)
{
    extern __shared__ char smem[];
    Ahi += (size_t)blockIdx.z * sA;  Alo += (size_t)blockIdx.z * sA;
    Bhi += (size_t)blockIdx.z * sB;  Blo += (size_t)blockIdx.z * sB;

    const int tid  = threadIdx.x;
    const int lane = tid & 31;
    const int wid  = tid >> 5;
    const int bm   = blockIdx.y * 256;
    const int bn   = blockIdx.x * 128;
    const int m_warp = (wid & 3) * 64;      // 4 warps along M (64 each)
    const int n_warp = (wid >> 2) * 64;     // 2 warps along N (64 each)

    const uint32_t sbase = smem_u32(smem);

    // ldmatrix per-lane byte offsets within a matrix tile
    const uint32_t aoff = (uint32_t)((m_warp + (lane & 15)) * (LDT * 2) + ((lane >> 4) * 8) * 2);
    const uint32_t boff = (uint32_t)((n_warp + (lane & 7) + ((lane & 16) ? 8 : 0)) * (LDT * 2)
                                     + ((lane & 8) ? 8 : 0) * 2);

    float acc[4][8][4];
    #pragma unroll
    for (int t = 0; t < 4; t++)
        #pragma unroll
        for (int n = 0; n < 8; n++)
            #pragma unroll
            for (int q = 0; q < 4; q++) acc[t][n][q] = 0.0f;

    const int nk = K / KC;

    // cp.async issue of one chunk into one stage buffer.
    auto issue = [&](int buf, int c) {
        const int k0 = c * KC;
        const uint32_t sb = sbase + buf * STAGE_B;
        // A: 256 rows x 8 chunks of 16B => 2048 insts, 8 per thread
        #pragma unroll
        for (int i = 0; i < 8; i++) {
            const int l   = tid + i * 256;
            const int row = l >> 3;
            const int ch  = (l & 7) * 16;
            const uint32_t soff = (uint32_t)(row * (LDT * 2)) + ch;
            const size_t ga = (size_t)(bm + row) * lda + k0;
            cpasync16(sb + OFF_AHI + soff, (const char*)(Ahi + ga) + ch);
            cpasync16(sb + OFF_ALO + soff, (const char*)(Alo + ga) + ch);
        }
        // B: 128 rows x 8 chunks => 1024 insts, 4 per thread
        #pragma unroll
        for (int i = 0; i < 4; i++) {
            const int l   = tid + i * 256;
            const int row = l >> 3;
            const int ch  = (l & 7) * 16;
            const uint32_t soff = (uint32_t)(row * (LDT * 2)) + ch;
            const size_t gb = (size_t)(bn + row) * ldb + k0;
            cpasync16(sb + OFF_BHI + soff, (const char*)(Bhi + gb) + ch);
            cpasync16(sb + OFF_BLO + soff, (const char*)(Blo + gb) + ch);
        }
    };

    // compute one chunk (4 ks-slabs of K=16)
    auto compute = [&](int buf) {
        const uint32_t base = sbase + buf * STAGE_B;
        #pragma unroll
        for (int ks = 0; ks < 4; ks++) {
            const uint32_t kb = (uint32_t)ks * 32;        // 16 bf16 = 32 B
            uint32_t bh[4][4], bl[4][4];
            #pragma unroll
            for (int u = 0; u < 4; u++) {
                ldsm4(bh[u][0], bh[u][1], bh[u][2], bh[u][3],
                      base + OFF_BHI + boff + u * (16 * LDT * 2) + kb);
                ldsm4(bl[u][0], bl[u][1], bl[u][2], bl[u][3],
                      base + OFF_BLO + boff + u * (16 * LDT * 2) + kb);
            }
            #pragma unroll
            for (int t = 0; t < 4; t++) {
                uint32_t ah[4], al[4];
                ldsm4(ah[0], ah[1], ah[2], ah[3],
                      base + OFF_AHI + aoff + t * (16 * LDT * 2) + kb);
                ldsm4(al[0], al[1], al[2], al[3],
                      base + OFF_ALO + aoff + t * (16 * LDT * 2) + kb);
                #pragma unroll
                for (int n = 0; n < 8; n++) {
                    const uint32_t* fh = &bh[n >> 1][(n & 1) * 2];
                    const uint32_t* fl = &bl[n >> 1][(n & 1) * 2];
                    mma16816(acc[t][n], ah, fh);   // hi*hi
                    mma16816(acc[t][n], ah, fl);   // hi*lo
                    mma16816(acc[t][n], al, fh);   // lo*hi
                }
            }
        }
    };

    // ---- pipeline: 2 stages, one barrier per chunk ----
    issue(0, 0);
    asm volatile("cp.async.commit_group;" ::: "memory");

    for (int c = 0; c < nk; ++c) {
        asm volatile("cp.async.wait_group 0;" ::: "memory");
        __syncthreads();
        if (c + 1 < nk) {
            issue((c + 1) & 1, c + 1);
            asm volatile("cp.async.commit_group;" ::: "memory");
        }
        compute(c & 1);
    }

    // ---- epilogue ----
    #pragma unroll
    for (int t = 0; t < 4; t++)
        #pragma unroll
        for (int n = 0; n < 8; n++) {
            const int row = bm + m_warp + t * 16 + (lane >> 2);
            const int col = bn + n_warp + n * 8 + (lane & 3) * 2;
            if (mode == 0) {
                float* C0 = Cf + (size_t)blockIdx.z * sC;
                *(float2*)(C0 + (size_t)row * ldc + col) =
                    make_float2(acc[t][n][0], acc[t][n][1]);
                *(float2*)(C0 + (size_t)(row + 8) * ldc + col) =
                    make_float2(acc[t][n][2], acc[t][n][3]);
            } else if (mode == 1) {
                bf162 h, l;
                split2(acc[t][n][0], acc[t][n][1], h, l);
                *(bf162*)(Chi + (size_t)row * ldc + col) = h;
                *(bf162*)(Clo + (size_t)row * ldc + col) = l;
                split2(acc[t][n][2], acc[t][n][3], h, l);
                *(bf162*)(Chi + (size_t)(row + 8) * ldc + col) = h;
                *(bf162*)(Clo + (size_t)(row + 8) * ldc + col) = l;
            } else {
                #pragma unroll
                for (int q = 0; q < 4; q++) {
                    const int r  = row + (q >> 1) * 8;
                    const int cc = col + (q & 1);
                    bf16 h = __float2bfloat16_rn(acc[t][n][q]);
                    bf16 l = __float2bfloat16_rn(acc[t][n][q] - __bfloat162float(h));
                    Chi[(size_t)cc * ldc + r] = h;
                    Clo[(size_t)cc * ldc + r] = l;
                }
            }
        }
}

// ---------------------------------------------------------------------------
// Row softmax over 4096 fp32 scores -> bf16 hi/lo probabilities.
// ---------------------------------------------------------------------------
__global__ __launch_bounds__(256) void softmax_split_kernel(
    const float* __restrict__ Sm, bf16* __restrict__ Phi, bf16* __restrict__ Plo)
{
    const float* row = Sm + (size_t)blockIdx.x * SLEN;
    bf16* ph = Phi + (size_t)blockIdx.x * SLEN;
    bf16* pl = Plo + (size_t)blockIdx.x * SLEN;
    const int t    = threadIdx.x;
    const int lane = t & 31;
    const int warp = t >> 5;

    __shared__ float red[8];

    float v[16];
    float mx = -1e30f;
    #pragma unroll
    for (int i = 0; i < 16; i++) {
        v[i] = row[t + (i << 8)];
        mx = fmaxf(mx, v[i]);
    }
    #pragma unroll
    for (int o = 16; o > 0; o >>= 1)
        mx = fmaxf(mx, __shfl_xor_sync(0xffffffffu, mx, o));
    if (lane == 0) red[warp] = mx;
    __syncthreads();
    float rmax = red[0];
    #pragma unroll
    for (int i = 1; i < 8; i++) rmax = fmaxf(rmax, red[i]);

    float sum = 0.0f;
    #pragma unroll
    for (int i = 0; i < 16; i++) {
        v[i] = __expf(v[i] - rmax);
        sum += v[i];
    }
    #pragma unroll
    for (int o = 16; o > 0; o >>= 1)
        sum += __shfl_xor_sync(0xffffffffu, sum, o);
    __syncthreads();
    if (lane == 0) red[warp] = sum;
    __syncthreads();
    float rsum = 0.0f;
    #pragma unroll
    for (int i = 0; i < 8; i++) rsum += red[i];

    const float inv = 1.0f / rsum;
    #pragma unroll
    for (int i = 0; i < 16; i++) {
        float p = v[i] * inv;
        bf16 h = __float2bfloat16_rn(p);
        ph[t + (i << 8)] = h;
        pl[t + (i << 8)] = __float2bfloat16_rn(p - __bfloat162float(h));
    }
}

// ---------------------------------------------------------------------------
// Final epilogue: y = attended + x;  out = y / ||y||_2 per 1024-row.
// ---------------------------------------------------------------------------
__global__ __launch_bounds__(256) void epilogue_kernel(
    const float* __restrict__ x, float* __restrict__ out)
{
    const size_t base = (size_t)blockIdx.x * DDIM;
    const int t    = threadIdx.x;
    const int lane = t & 31;
    const int warp = t >> 5;

    __shared__ float red[8];

    float4 a  = *(const float4*)(out + base + t * 4);
    float4 xv = *(const float4*)(x   + base + t * 4);
    float y0 = a.x + xv.x, y1 = a.y + xv.y, y2 = a.z + xv.z, y3 = a.w + xv.w;

    float ss = y0 * y0 + y1 * y1 + y2 * y2 + y3 * y3;
    #pragma unroll
    for (int o = 16; o > 0; o >>= 1)
        ss += __shfl_xor_sync(0xffffffffu, ss, o);
    if (lane == 0) red[warp] = ss;
    __syncthreads();
    float tot = 0.0f;
    #pragma unroll
    for (int i = 0; i < 8; i++) tot += red[i];

    const float inv = 1.0f / sqrtf(tot);
    *(float4*)(out + base + t * 4) =
        make_float4(y0 * inv, y1 * inv, y2 * inv, y3 * inv);
}

// ---------------------------------------------------------------------------
// Launch
// ---------------------------------------------------------------------------
extern "C" void kernel_launch(void* const* d_in, const int* in_sizes, int n_in,
                              void* d_out, int out_size)
{
    const float* x  = (const float*)d_in[0];
    const float* Wq = (const float*)d_in[1];
    const float* Wk = (const float*)d_in[2];
    const float* Wv = (const float*)d_in[3];
    float* out = (float*)d_out;

    bf16 *xhi, *xlo, *Wqhi, *Wqlo, *Wkhi, *Wklo, *Wvhi, *Wvlo;
    bf16 *Qhi, *Qlo, *Khi, *Klo, *Vthi, *Vtlo, *Phi, *Plo;
    float* Sc;
    cudaGetSymbolAddress((void**)&xhi,  g_xhi);   cudaGetSymbolAddress((void**)&xlo,  g_xlo);
    cudaGetSymbolAddress((void**)&Wqhi, g_Wqhi);  cudaGetSymbolAddress((void**)&Wqlo, g_Wqlo);
    cudaGetSymbolAddress((void**)&Wkhi, g_Wkhi);  cudaGetSymbolAddress((void**)&Wklo, g_Wklo);
    cudaGetSymbolAddress((void**)&Wvhi, g_Wvhi);  cudaGetSymbolAddress((void**)&Wvlo, g_Wvlo);
    cudaGetSymbolAddress((void**)&Qhi,  g_Qhi);   cudaGetSymbolAddress((void**)&Qlo,  g_Qlo);
    cudaGetSymbolAddress((void**)&Khi,  g_Khi);   cudaGetSymbolAddress((void**)&Klo,  g_Klo);
    cudaGetSymbolAddress((void**)&Vthi, g_Vthi);  cudaGetSymbolAddress((void**)&Vtlo, g_Vtlo);
    cudaGetSymbolAddress((void**)&Phi,  g_Phi);   cudaGetSymbolAddress((void**)&Plo,  g_Plo);
    cudaGetSymbolAddress((void**)&Sc,   g_S);

    cudaFuncSetAttribute(gemm_bf, cudaFuncAttributeMaxDynamicSharedMemorySize, SMEM_DYN);

    const size_t sQKV = (size_t)SLEN * DDIM;
    const size_t sSS  = (size_t)SLEN * SLEN;
    dim3 blk(256);

    // 0) split inputs to bf16 hi/lo
    conv_split<<<(MTOT * DDIM) / 1024, blk>>>(x,  xhi,  xlo);
    conv_split<<<(DDIM * DDIM) / 1024, blk>>>(Wq, Wqhi, Wqlo);
    conv_split<<<(DDIM * DDIM) / 1024, blk>>>(Wk, Wkhi, Wklo);
    conv_split<<<(DDIM * DDIM) / 1024, blk>>>(Wv, Wvhi, Wvlo);

    // 1) projections (NT): Q/K as hi/lo pairs; V written transposed hi/lo
    dim3 gqkv(DDIM / 128, MTOT / 256, 1);    // (8, 64)
    gemm_bf<<<gqkv, blk, SMEM_DYN>>>(xhi, xlo, Wqhi, Wqlo, nullptr, Qhi, Qlo,
                                     DDIM, DDIM, DDIM, DDIM, 1, 0, 0, 0);
    gemm_bf<<<gqkv, blk, SMEM_DYN>>>(xhi, xlo, Wkhi, Wklo, nullptr, Khi, Klo,
                                     DDIM, DDIM, DDIM, DDIM, 1, 0, 0, 0);
    gemm_bf<<<gqkv, blk, SMEM_DYN>>>(xhi, xlo, Wvhi, Wvlo, nullptr, Vthi, Vtlo,
                                     DDIM, DDIM, MTOT, DDIM, 2, 0, 0, 0);

    // 2) scores = Q @ K^T per batch (fp32 out)
    dim3 gsc(SLEN / 128, SLEN / 256, BATCH); // (32, 16, 4)
    gemm_bf<<<gsc, blk, SMEM_DYN>>>(Qhi, Qlo, Khi, Klo, Sc, nullptr, nullptr,
                                    DDIM, DDIM, SLEN, DDIM, 0, sQKV, sQKV, sSS);

    // 3) softmax -> P hi/lo (BETA = 1)
    softmax_split_kernel<<<MTOT, blk>>>(Sc, Phi, Plo);

    // 4) attended = P @ Vt^T per batch (fp32 out into d_out)
    dim3 gav(DDIM / 128, SLEN / 256, BATCH); // (8, 16, 4)
    gemm_bf<<<gav, blk, SMEM_DYN>>>(Phi, Plo, Vthi, Vtlo, out, nullptr, nullptr,
                                    SLEN, MTOT, DDIM, SLEN, 0,
                                    sSS, (size_t)SLEN, sQKV);

    // 5) y = attended + x; L2 normalize
    epilogue_kernel<<<MTOT, blk>>>(x, out);
}